// round 17
// baseline (speedup 1.0000x reference)
#include <cuda_runtime.h>
#include <cuda_fp16.h>
#include <math.h>
#include <stdint.h>

#define HH      224
#define C_      192
#define NPIX    49
#define HEADS   6
#define NWIN    8192
#define ATT_W   14406
#define NTHR    768

// ---- smem byte layout (211 KB, 1 CTA/SM, two windows per CTA) ----
#define IMG_X   0          // x A-image, M=128 (49152); VF aliases after V-GEMM
#define IMG_Y   49152      // y A-image (49152); CTX frags alias during attention
#define B_OFF   98304      // B staging, double buffer 2 x 12288
#define QF_HI   122880     // 49152
#define KF_HI   172032     // 43008 (2 windows x 21504)
#define LOGMW_O 215040     // 2 x 56 floats
#define GOFF_O  215488     // 2 x 64 ints
#define SMEM_BYTES 216064
#define VF_HI   0          // 49152 (2 windows)
#define CTX_OFF 49152

// weight images (f16 hi only) in mma-B-fragment order: [w][chunk][12288]
__device__ __align__(16) __half g_Bimg[4][3][12288];

// ---------------- helpers ----------------
__device__ __forceinline__ void mma16816(float* c, const uint32_t* a, uint32_t b0, uint32_t b1) {
    asm volatile("mma.sync.aligned.m16n8k16.row.col.f32.f16.f16.f32 "
        "{%0,%1,%2,%3}, {%4,%5,%6,%7}, {%8,%9}, {%0,%1,%2,%3};"
        : "+f"(c[0]), "+f"(c[1]), "+f"(c[2]), "+f"(c[3])
        : "r"(a[0]), "r"(a[1]), "r"(a[2]), "r"(a[3]), "r"(b0), "r"(b1));
}
__device__ __forceinline__ uint32_t cvt2(float a, float b) {
    __half2 h2 = __float22half2_rn(make_float2(a, b));
    return *(uint32_t*)&h2;
}
__device__ __forceinline__ void stcs1(float* p, float v) {
    asm volatile("st.global.cs.f32 [%0], %1;" :: "l"(p), "f"(v) : "memory");
}
__device__ __forceinline__ void stcs2(float* p, float2 v) {
    asm volatile("st.global.cs.v2.f32 [%0], {%1,%2};" :: "l"(p), "f"(v.x), "f"(v.y) : "memory");
}

// ---------------- prep: weights -> f16 fragment-order images ----------------
__global__ void prep_w(const float* __restrict__ Wq, const float* __restrict__ Wk,
                       const float* __restrict__ Wv, const float* __restrict__ Wo)
{
    int e = blockIdx.x * 256 + threadIdx.x;
    if (e >= 4 * 36864) return;
    int wsel = e / 36864, r = e % 36864;
    int k = r / 192, n = r % 192;
    const float* W = (wsel == 0) ? Wq : (wsel == 1) ? Wk : (wsel == 2) ? Wv : Wo;
    __half h = __float2half_rn(W[k * 192 + n]);
    int chunk = k >> 6, kk = k & 63;
    int kt = kk >> 4, kc = kk & 15;
    int khi = kc >> 3, t = (kc & 7) >> 1, half = kc & 1;
    int ntile = n >> 3, g = n & 7;
    int lane = g * 4 + t;
    int off = ((kt * 24 + ntile) * 32 + lane) * 4 + khi * 2 + half;
    g_Bimg[wsel][chunk][off] = h;
}

// stage A element pair (hi only); p in [0,128)
__device__ __forceinline__ void stage_hi(char* smem, int base, int p, int c, float a0, float a1)
{
    uint32_t hi = cvt2(a0, a1);
    int mt = p >> 4, rr = p & 15;
    int g = rr & 7, hi8 = rr >> 3;
    int kt = c >> 4, cc = c & 15;
    int khi = cc >> 3, t = (cc & 7) >> 1;
    int reg = hi8 + 2 * khi;
    int off = (((kt * 8 + mt) * 32 + g * 4 + t) * 8 + reg * 2) * 2;
    *(uint32_t*)(smem + base + off) = hi;
}

// ---- 24-warp GEMM, M=128 (two windows), double-buffered B, 1 bar/stage.
// mode: 0 = direct gmem out (O), 1 = Q frags, 2 = K frags, 3 = VF frags (V)
__device__ void run_gemm(char* smem, const __half* img, int a_base,
                         float* __restrict__ gout, const int* s_goff,
                         int tx, int mode, uint4& wreg)
{
    const int wid = tx >> 5, lane = tx & 31;
    const int mtp = wid / 6, jg = wid % 6;   // mtp 0..3, jg 0..5
    const int g = lane >> 2, t = lane & 3;

    float c[2][4][4];
    #pragma unroll
    for (int m2 = 0; m2 < 2; m2++)
        #pragma unroll
        for (int jj = 0; jj < 4; jj++)
            #pragma unroll
            for (int i = 0; i < 4; i++) c[m2][jj][i] = 0.0f;

    for (int hs = 0; hs < 6; hs++) {
        char* buf = smem + B_OFF + (hs & 1) * 12288;
        ((uint4*)buf)[tx] = wreg;
        if (hs < 5)
            wreg = ((const uint4*)(img + (hs + 1) * 6144))[tx];
        __syncthreads();
        #pragma unroll
        for (int ktl = 0; ktl < 2; ktl++) {
            const int kt = hs * 2 + ktl;
            uint4 ah0 = *(const uint4*)(smem + a_base + ((kt * 8 + 2 * mtp)     * 32 + lane) * 16);
            uint4 ah1 = *(const uint4*)(smem + a_base + ((kt * 8 + 2 * mtp + 1) * 32 + lane) * 16);
            #pragma unroll
            for (int jj = 0; jj < 4; jj++) {
                uint2 b = *(const uint2*)(buf + ((ktl * 24 + jg * 4 + jj) * 32 + lane) * 8);
                mma16816(c[0][jj], (const uint32_t*)&ah0, b.x, b.y);
                mma16816(c[1][jj], (const uint32_t*)&ah1, b.x, b.y);
            }
        }
    }

    if (mode == 0) {
        // O: direct gmem stores; rows mtg*16+g, window = row>>6, local row <49 valid
        #pragma unroll
        for (int m2 = 0; m2 < 2; m2++) {
            const int mtg = 2 * mtp + m2;
            const int r0 = mtg * 16 + g, r1 = r0 + 8;
            const int win = r0 >> 6;
            const int rl0 = r0 & 63, rl1 = r1 & 63;
            int o0 = (rl0 < NPIX) ? s_goff[win * 64 + rl0] : 0;
            int o1 = (rl1 < NPIX) ? s_goff[win * 64 + rl1] : 0;
            #pragma unroll
            for (int jj = 0; jj < 4; jj++) {
                int col = (jg * 4 + jj) * 8 + 2 * t;
                if (rl0 < NPIX) stcs2(gout + o0 + col, make_float2(c[m2][jj][0], c[m2][jj][1]));
                if (rl1 < NPIX) stcs2(gout + o1 + col, make_float2(c[m2][jj][2], c[m2][jj][3]));
            }
        }
    } else if (mode == 1) {
        // Q: scale -> A-fragment image. h = jg, kb = jj>>1.
        const float SCALE = 0.17677669529663687f;
        #pragma unroll
        for (int m2 = 0; m2 < 2; m2++) {
            const int mtg = 2 * mtp + m2;
            #pragma unroll
            for (int kb = 0; kb < 2; kb++) {
                uint32_t w0 = cvt2(c[m2][2*kb][0]*SCALE,   c[m2][2*kb][1]*SCALE);
                uint32_t w1 = cvt2(c[m2][2*kb][2]*SCALE,   c[m2][2*kb][3]*SCALE);
                uint32_t w2 = cvt2(c[m2][2*kb+1][0]*SCALE, c[m2][2*kb+1][1]*SCALE);
                uint32_t w3 = cvt2(c[m2][2*kb+1][2]*SCALE, c[m2][2*kb+1][3]*SCALE);
                int off = (((jg * 8 + mtg) * 2 + kb) * 32 + lane) * 16;
                *(uint4*)(smem + QF_HI + off) = make_uint4(w0, w1, w2, w3);
            }
        }
    } else if (mode == 2) {
        // K -> B-fragment image (packed khi pair). win = mtg>>2, ntl = 2*(mtg&3)+rh, guard ntl<7.
        #pragma unroll
        for (int m2 = 0; m2 < 2; m2++) {
            const int mtg = 2 * mtp + m2;
            const int win = mtg >> 2, ntl0 = 2 * (mtg & 3);
            #pragma unroll
            for (int kb = 0; kb < 2; kb++) {
                uint32_t a0 = cvt2(c[m2][2*kb][0],   c[m2][2*kb][1]);
                uint32_t b0 = cvt2(c[m2][2*kb+1][0], c[m2][2*kb+1][1]);
                uint32_t a1 = cvt2(c[m2][2*kb][2],   c[m2][2*kb][3]);
                uint32_t b1 = cvt2(c[m2][2*kb+1][2], c[m2][2*kb+1][3]);
                int base0 = (((win * 12 + jg * 2 + kb) * 7 + ntl0) * 32 + lane) * 8;
                *(uint2*)(smem + KF_HI + base0) = make_uint2(a0, b0);
                if ((mtg & 3) < 3)
                    *(uint2*)(smem + KF_HI + base0 + 256) = make_uint2(a1, b1);
            }
        }
    } else {
        // V: direct B-fragment store. Lane pairing rows (g, g^1) via shfl_xor lane^4.
        const int even = !(g & 1);
        const int tt = g >> 1;
        #pragma unroll
        for (int m2 = 0; m2 < 2; m2++) {
            const int mtg = 2 * mtp + m2;
            const int win = mtg >> 2, ktl = mtg & 3;
            #pragma unroll
            for (int jj = 0; jj < 4; jj++) {
                int col = (jg * 4 + jj) * 8 + 2 * t;
                float p0 = __shfl_xor_sync(0xffffffffu, c[m2][jj][0], 4);
                float p1 = __shfl_xor_sync(0xffffffffu, c[m2][jj][1], 4);
                float p2 = __shfl_xor_sync(0xffffffffu, c[m2][jj][2], 4);
                float p3 = __shfl_xor_sync(0xffffffffu, c[m2][jj][3], 4);
                int m0l = 16 * ktl + (even ? g : g - 1);   // local row within window
                float va0 = even ? c[m2][jj][0] : p1;
                float vb0 = even ? p0 : c[m2][jj][1];
                float va1 = even ? c[m2][jj][2] : p3;
                float vb1 = even ? p2 : c[m2][jj][3];
                va0 = (m0l     < NPIX) ? va0 : 0.0f;
                vb0 = (m0l + 1 < NPIX) ? vb0 : 0.0f;
                va1 = (m0l + 8 < NPIX) ? va1 : 0.0f;
                vb1 = (m0l + 9 < NPIX) ? vb1 : 0.0f;
                int ch = col + (even ? 0 : 1);
                uint32_t h0 = cvt2(va0, vb0);
                uint32_t h1 = cvt2(va1, vb1);
                int hh = ch >> 5, nt2 = (ch >> 3) & 3, gg = ch & 7;
                int id = (((win * 6 + hh) * 4 + ktl) * 4 + nt2) * 32 + gg * 4 + tt;
                *(uint2*)(smem + VF_HI + id * 8) = make_uint2(h0, h1);
            }
        }
    }
}

__global__ __launch_bounds__(NTHR, 1)
void fused_winattn(const float* __restrict__ x, const float* __restrict__ y,
                   float* __restrict__ out, float* __restrict__ att_out)
{
    extern __shared__ __align__(16) char smem[];
    float* s_logmw = (float*)(smem + LOGMW_O);
    int*   s_goff  = (int*)(smem + GOFF_O);

    const int tx = threadIdx.x;
    const int wid = tx >> 5, lane = tx & 31;
    const int w0 = 2 * blockIdx.x;

    // ---- prefetch Q's B half-chunk 0 ----
    uint4 wreg = ((const uint4*)&g_Bimg[0][0][0])[tx];

    // ---- gather both windows: x (roll + mask) and y -> A-images ----
    for (int pp = wid; pp < 2 * NPIX; pp += 24) {
        int win = (pp >= NPIX) ? 1 : 0;
        int local = pp - win * NPIX;
        int p_img = win * 64 + local;
        int w = w0 + win;
        int b  = w >> 10, wr = (w >> 5) & 31, wc = w & 31;
        int i = local / 7, j = local - i * 7;
        int hs = wr * 7 + i + 3;  if (hs >= HH) hs -= HH;
        int vs = wc * 7 + j + 3;  if (vs >= HH) vs -= HH;
        int goff = ((b * HH + hs) * HH + vs) * C_;
        float2 xv[3], yv[3];
        int cnt = 0;
        #pragma unroll
        for (int u = 0; u < 3; u++) {
            xv[u] = *(const float2*)(x + goff + 2 * lane + 64 * u);
            yv[u] = *(const float2*)(y + goff + 2 * lane + 64 * u);
            cnt += (xv[u].x > 0.95f ? 0 : 1) + (xv[u].y > 0.95f ? 0 : 1);
        }
        #pragma unroll
        for (int o = 16; o; o >>= 1) cnt += __shfl_xor_sync(0xffffffffu, cnt, o);
        float mask = (float)cnt * (1.0f / 192.0f);
        #pragma unroll
        for (int u = 0; u < 3; u++) {
            stage_hi(smem, IMG_X, p_img, 2 * lane + 64 * u, xv[u].x * mask, xv[u].y * mask);
            stage_hi(smem, IMG_Y, p_img, 2 * lane + 64 * u, yv[u].x, yv[u].y);
        }
        if (lane == 0) {
            s_logmw[win * 56 + local] = logf(mask + 1e-6f);
            s_goff[win * 64 + local]  = goff;
        }
    }
    // (no barrier needed: Q-GEMM's stage-0 bar orders IMG writes before compute)

    // ---- GEMM q -> Q frags (reads IMG_X) ----
    run_gemm(smem, &g_Bimg[0][0][0], IMG_X, nullptr, nullptr, tx, 1, wreg);
    wreg = ((const uint4*)&g_Bimg[1][0][0])[tx];

    // ---- GEMM k -> K frags (reads IMG_Y) ----
    run_gemm(smem, &g_Bimg[1][0][0], IMG_Y, nullptr, nullptr, tx, 2, wreg);
    wreg = ((const uint4*)&g_Bimg[2][0][0])[tx];

    // ---- GEMM v -> VF frags (reads IMG_Y, writes VF into IMG_X region) ----
    run_gemm(smem, &g_Bimg[2][0][0], IMG_Y, nullptr, nullptr, tx, 3, wreg);
    wreg = ((const uint4*)&g_Bimg[3][0][0])[tx];   // O's B, lives through attention
    __syncthreads();   // QF/KF/VF complete before attention

    // ---- fused attention per (win, h, mt); h = wid>>2, mt = wid&3 ----
    {
        const int g = lane >> 2, t = lane & 3;
        const int h = wid >> 2, mt = wid & 3;
        #pragma unroll
        for (int win = 0; win < 2; win++) {
            const int mtg = win * 4 + mt;
            const int n0 = mt * 16 + g;                 // local row
            const float* lmw = s_logmw + win * 56;
            uint4 qh0 = *(const uint4*)(smem + QF_HI + (((h * 8 + mtg) * 2 + 0) * 32 + lane) * 16);
            uint4 qh1 = *(const uint4*)(smem + QF_HI + (((h * 8 + mtg) * 2 + 1) * 32 + lane) * 16);
            float c[7][4];
            #pragma unroll
            for (int nt = 0; nt < 7; nt++) {
                uint2 bh0 = *(const uint2*)(smem + KF_HI + (((win * 12 + h * 2 + 0) * 7 + nt) * 32 + lane) * 8);
                uint2 bh1 = *(const uint2*)(smem + KF_HI + (((win * 12 + h * 2 + 1) * 7 + nt) * 32 + lane) * 8);
                c[nt][0] = c[nt][1] = c[nt][2] = c[nt][3] = 0.0f;
                mma16816(c[nt], (const uint32_t*)&qh0, bh0.x, bh0.y);
                mma16816(c[nt], (const uint32_t*)&qh1, bh1.x, bh1.y);
            }
            #pragma unroll
            for (int nt = 0; nt < 6; nt++) {
                float lmx = lmw[8 * nt + 2 * t], lmy = lmw[8 * nt + 2 * t + 1];
                c[nt][0] += lmx; c[nt][1] += lmy;
                c[nt][2] += lmx; c[nt][3] += lmy;
            }
            {
                float lm48 = lmw[48];
                c[6][0] = (t == 0) ? c[6][0] + lm48 : -1e30f;
                c[6][2] = (t == 0) ? c[6][2] + lm48 : -1e30f;
                c[6][1] = -1e30f;  c[6][3] = -1e30f;
            }
            float mx0 = -1e30f, mx1 = -1e30f;
            #pragma unroll
            for (int nt = 0; nt < 7; nt++) {
                mx0 = fmaxf(mx0, fmaxf(c[nt][0], c[nt][1]));
                mx1 = fmaxf(mx1, fmaxf(c[nt][2], c[nt][3]));
            }
            mx0 = fmaxf(mx0, __shfl_xor_sync(0xffffffffu, mx0, 1));
            mx0 = fmaxf(mx0, __shfl_xor_sync(0xffffffffu, mx0, 2));
            mx1 = fmaxf(mx1, __shfl_xor_sync(0xffffffffu, mx1, 1));
            mx1 = fmaxf(mx1, __shfl_xor_sync(0xffffffffu, mx1, 2));
            float s0 = 0.0f, s1 = 0.0f;
            #pragma unroll
            for (int nt = 0; nt < 7; nt++) {
                c[nt][0] = __expf(c[nt][0] - mx0); s0 += c[nt][0];
                c[nt][1] = __expf(c[nt][1] - mx0); s0 += c[nt][1];
                c[nt][2] = __expf(c[nt][2] - mx1); s1 += c[nt][2];
                c[nt][3] = __expf(c[nt][3] - mx1); s1 += c[nt][3];
            }
            s0 += __shfl_xor_sync(0xffffffffu, s0, 1);
            s0 += __shfl_xor_sync(0xffffffffu, s0, 2);
            s1 += __shfl_xor_sync(0xffffffffu, s1, 1);
            s1 += __shfl_xor_sync(0xffffffffu, s1, 2);
            float inv0 = 1.0f / s0, inv1 = 1.0f / s1;
            #pragma unroll
            for (int nt = 0; nt < 7; nt++) {
                c[nt][0] *= inv0; c[nt][1] *= inv0;
                c[nt][2] *= inv1; c[nt][3] *= inv1;
            }
            {
                float* ab = att_out + (size_t)(w0 + win) * ATT_W + h * 2401;
                #pragma unroll
                for (int nt = 0; nt < 7; nt++) {
                    int m0 = 8 * nt + 2 * t;
                    if (n0 < NPIX) {
                        if (m0     < NPIX) stcs1(ab + n0 * NPIX + m0,     c[nt][0]);
                        if (m0 + 1 < NPIX) stcs1(ab + n0 * NPIX + m0 + 1, c[nt][1]);
                    }
                    if (n0 + 8 < NPIX) {
                        if (m0     < NPIX) stcs1(ab + (n0 + 8) * NPIX + m0,     c[nt][2]);
                        if (m0 + 1 < NPIX) stcs1(ab + (n0 + 8) * NPIX + m0 + 1, c[nt][3]);
                    }
                }
            }
            // att@v via mma (1-pass)
            float d[4][4];
            #pragma unroll
            for (int n2 = 0; n2 < 4; n2++)
                d[n2][0] = d[n2][1] = d[n2][2] = d[n2][3] = 0.0f;
            #pragma unroll
            for (int kt = 0; kt < 4; kt++) {
                uint32_t Ah[4];
                Ah[0] = cvt2(c[2*kt][0], c[2*kt][1]);
                Ah[1] = cvt2(c[2*kt][2], c[2*kt][3]);
                if (2 * kt + 1 < 7) {
                    Ah[2] = cvt2(c[2*kt+1][0], c[2*kt+1][1]);
                    Ah[3] = cvt2(c[2*kt+1][2], c[2*kt+1][3]);
                } else {
                    Ah[2] = Ah[3] = 0u;
                }
                #pragma unroll
                for (int n2 = 0; n2 < 4; n2++) {
                    uint2 bh = *(const uint2*)(smem + VF_HI + ((((win * 6 + h) * 4 + kt) * 4 + n2) * 32 + lane) * 8);
                    mma16816(d[n2], Ah, bh.x, bh.y);
                }
            }
            // ctx -> A-fragment image for GEMM o (rows mtg*16+...)
            #pragma unroll
            for (int n2 = 0; n2 < 4; n2++) {
                uint32_t h0 = cvt2(d[n2][0], d[n2][1]);
                uint32_t h1 = cvt2(d[n2][2], d[n2][3]);
                int kt_o = 2 * h + (n2 >> 1);
                int khi  = n2 & 1;
                int off  = ((kt_o * 8 + mtg) * 32 + lane) * 16 + khi * 8;
                *(uint2*)(smem + CTX_OFF + off) = make_uint2(h0, h1);
            }
        }
    }
    // (O-GEMM's stage-0 bar orders CTX writes before compute)

    // ---- GEMM o (A = ctx frags) -> direct gmem stores ----
    run_gemm(smem, &g_Bimg[3][0][0], CTX_OFF, out, s_goff, tx, 0, wreg);
}

extern "C" void kernel_launch(void* const* d_in, const int* in_sizes, int n_in,
                              void* d_out, int out_size)
{
    const float* x  = (const float*)d_in[0];
    const float* y  = (const float*)d_in[1];
    const float* Wq = (const float*)d_in[2];
    const float* Wk = (const float*)d_in[3];
    const float* Wv = (const float*)d_in[4];
    const float* Wo = (const float*)d_in[5];

    float* out = (float*)d_out;                       // [8,224,224,192]
    float* att = out + (size_t)8 * 224 * 224 * 192;   // [8192,6,49,49]

    prep_w<<<576, 256>>>(Wq, Wk, Wv, Wo);

    cudaFuncSetAttribute(fused_winattn,
                         cudaFuncAttributeMaxDynamicSharedMemorySize, SMEM_BYTES);
    fused_winattn<<<NWIN / 2, NTHR, SMEM_BYTES>>>(x, y, out, att);
}